// round 2
// baseline (speedup 1.0000x reference)
#include <cuda_runtime.h>

// PennyLaneSimpleClassifier: 12-qubit state-vector sim, batch 4096.
// One CTA per batch element; state (4096 complex) lives in shared memory
// split into re/im float arrays with +1-word-per-32 padding.
//
// Circuit structure exploited:
//  - RY embedding == product state -> built from two 64-entry subproduct tables.
//  - RZ*RX*RZ fused into one 2x2 unitary per (layer, qubit)  (48 gates total).
//  - Adjacent-CNOT chain == Gray-code permutation: new[j] = old[j ^ (j>>1)].
//  - Each smem pass handles 4 qubits: thread owns 16 amplitudes, applies 4
//    register-resident butterfly stages. 3 gate passes + 1 perm per layer.
//  - Final permutation folded into the measurement read.

#define NQ 12
#define DIM 4096
#define NL 4
#define NOUT 10
#define NTHREADS 256
#define NWARPS (NTHREADS / 32)

__device__ __forceinline__ int pa(int i) { return i + (i >> 5); }  // bank-conflict padding

__device__ __forceinline__ float2 cmul(float2 a, float2 b) {
    return make_float2(fmaf(a.x, b.x, -a.y * b.y), fmaf(a.x, b.y, a.y * b.x));
}
__device__ __forceinline__ float2 cfma(float2 a, float2 b, float2 acc) {
    acc.x = fmaf(a.x, b.x, fmaf(-a.y, b.y, acc.x));
    acc.y = fmaf(a.x, b.y, fmaf(a.y, b.x, acc.y));
    return acc;
}

// Apply 4 butterfly stages (bits kb..kb+3) to a register-resident 16-amp group.
__device__ __forceinline__ void apply4(float2 amp[16], const float2 (*Ul)[4], int kb) {
#pragma unroll
    for (int s = 0; s < 4; s++) {
        int qub = 11 - (kb + s);              // amplitude bit (kb+s) == qubit 11-(kb+s)
        float2 m00 = Ul[qub][0];
        float2 m01 = Ul[qub][1];
        float2 m10 = Ul[qub][2];
        float2 m11 = Ul[qub][3];
#pragma unroll
        for (int v = 0; v < 16; v++) {
            if (v & (1 << s)) continue;
            float2 x0 = amp[v];
            float2 x1 = amp[v + (1 << s)];
            float2 y0 = cmul(m00, x0); y0 = cfma(m01, x1, y0);
            float2 y1 = cmul(m10, x0); y1 = cfma(m11, x1, y1);
            amp[v] = y0;
            amp[v + (1 << s)] = y1;
        }
    }
}

__global__ __launch_bounds__(NTHREADS)
void qsim_kernel(const float* __restrict__ x, const float* __restrict__ theta,
                 const float* __restrict__ W, const float* __restrict__ bias,
                 float* __restrict__ out)
{
    __shared__ float sRe[DIM + (DIM >> 5)];
    __shared__ float sIm[DIM + (DIM >> 5)];
    __shared__ float2 U[NL][NQ][4];
    __shared__ float prodLo[64], prodHi[64];
    __shared__ float cx[NQ], sx[NQ];
    __shared__ float zPart[NWARPS][NQ];
    __shared__ float zFin[NQ];

    const int b = blockIdx.x;
    const int t = threadIdx.x;

    // ---- fused RZ(c)*RX(bb)*RZ(a) gate matrices (48 of them) ----
    if (t < NL * NQ) {
        float a  = theta[3 * t + 0];
        float bb = theta[3 * t + 1];
        float c  = theta[3 * t + 2];
        float sh, ch;   sincosf(0.5f * bb, &sh, &ch);
        float sap, cap; sincosf(0.5f * (a + c), &sap, &cap);
        float sam, cam; sincosf(0.5f * (a - c), &sam, &cam);
        int l = t / NQ, q = t - l * NQ;
        U[l][q][0] = make_float2( ch * cap, -ch * sap);   // U00 =  cb e^{-i(a+c)/2}
        U[l][q][1] = make_float2( sh * sam, -sh * cam);   // U01 = -i sb e^{ i(a-c)/2}
        U[l][q][2] = make_float2(-sh * sam, -sh * cam);   // U10 = -i sb e^{-i(a-c)/2}
        U[l][q][3] = make_float2( ch * cap,  ch * sap);   // U11 =  cb e^{ i(a+c)/2}
    }
    // ---- RY embedding angles: cos/sin of x*pi/2 ----
    if (t < NQ) {
        float s, c;
        sincosf(x[b * NQ + t] * 1.57079632679489662f, &s, &c);
        sx[t] = s; cx[t] = c;
    }
    __syncthreads();

    // ---- subproduct tables for the product state ----
    if (t < 128) {
        int v = t & 63;
        float p = 1.0f;
        if (t < 64) {
            // amplitude bits 0..5 -> qubits 11..6
#pragma unroll
            for (int j = 0; j < 6; j++) p *= ((v >> j) & 1) ? sx[11 - j] : cx[11 - j];
            prodLo[v] = p;
        } else {
            // amplitude bits 6..11 -> qubits 5..0
#pragma unroll
            for (int j = 0; j < 6; j++) p *= ((v >> j) & 1) ? sx[5 - j] : cx[5 - j];
            prodHi[v] = p;
        }
    }

    float2 amp[16];
    const int g = t;  // group id: 256 groups of 16 amps

    for (int l = 0; l < NL; l++) {
        // ======== pass kb=8 : bits 8..11 (qubits 3..0) ========
        __syncthreads();
        if (l == 0) {
            // synthesize product state directly (init pass folded in)
#pragma unroll
            for (int v = 0; v < 16; v++) {
                int i = g + (v << 8);
                amp[v] = make_float2(prodHi[i >> 6] * prodLo[i & 63], 0.0f);
            }
        } else {
#pragma unroll
            for (int v = 0; v < 16; v++) {
                int idx = pa(g + (v << 8));
                amp[v] = make_float2(sRe[idx], sIm[idx]);
            }
        }
        apply4(amp, U[l], 8);
#pragma unroll
        for (int v = 0; v < 16; v++) {
            int idx = pa(g + (v << 8));
            sRe[idx] = amp[v].x; sIm[idx] = amp[v].y;
        }

        // ======== pass kb=4 : bits 4..7 (qubits 7..4) ========
        __syncthreads();
        {
            int ib = ((g >> 4) << 8) | (g & 15);
#pragma unroll
            for (int v = 0; v < 16; v++) {
                int idx = pa(ib + (v << 4));
                amp[v] = make_float2(sRe[idx], sIm[idx]);
            }
            apply4(amp, U[l], 4);
#pragma unroll
            for (int v = 0; v < 16; v++) {
                int idx = pa(ib + (v << 4));
                sRe[idx] = amp[v].x; sIm[idx] = amp[v].y;
            }
        }

        // ======== pass kb=0 : bits 0..3 (qubits 11..8) ========
        __syncthreads();
        {
            int ib = g << 4;
#pragma unroll
            for (int v = 0; v < 16; v++) {
                int idx = pa(ib + v);
                amp[v] = make_float2(sRe[idx], sIm[idx]);
            }
            apply4(amp, U[l], 0);
#pragma unroll
            for (int v = 0; v < 16; v++) {
                int idx = pa(ib + v);
                sRe[idx] = amp[v].x; sIm[idx] = amp[v].y;
            }
        }

        // ======== CNOT chain == Gray-code permutation ========
        if (l < NL - 1) {
            __syncthreads();
            float2 tmp[16];
#pragma unroll
            for (int m = 0; m < 16; m++) {
                int j = t + (m << 8);
                int idx = pa(j ^ (j >> 1));
                tmp[m] = make_float2(sRe[idx], sIm[idx]);
            }
            __syncthreads();
#pragma unroll
            for (int m = 0; m < 16; m++) {
                int idx = pa(t + (m << 8));
                sRe[idx] = tmp[m].x; sIm[idx] = tmp[m].y;
            }
        }
    }

    // ======== measurement (final permutation folded into the read) ========
    __syncthreads();
    // j = t + 256*m : bits 0..7 fixed per thread (qubits 4..11),
    //                 bits 8..11 = m (qubits 3..0, compile-time signs).
    float ptot = 0.0f, z0 = 0.0f, z1 = 0.0f, z2 = 0.0f, z3 = 0.0f;
#pragma unroll
    for (int m = 0; m < 16; m++) {
        int j = t + (m << 8);
        int idx = pa(j ^ (j >> 1));      // read the post-CNOT state
        float re = sRe[idx], im = sIm[idx];
        float pr = fmaf(re, re, im * im);
        ptot += pr;
        z0 += (m & 8) ? -pr : pr;        // qubit 0 = bit 11 = m bit 3
        z1 += (m & 4) ? -pr : pr;        // qubit 1
        z2 += (m & 2) ? -pr : pr;        // qubit 2
        z3 += (m & 1) ? -pr : pr;        // qubit 3
    }
    float zacc[NQ];
    zacc[0] = z0; zacc[1] = z1; zacc[2] = z2; zacc[3] = z3;
#pragma unroll
    for (int q = 4; q < NQ; q++)
        zacc[q] = ((t >> (11 - q)) & 1) ? -ptot : ptot;   // qubits 4..11 from thread bits

    // warp reduction, then cross-warp
#pragma unroll
    for (int q = 0; q < NQ; q++) {
        float v = zacc[q];
#pragma unroll
        for (int o = 16; o > 0; o >>= 1) v += __shfl_xor_sync(0xffffffffu, v, o);
        if ((t & 31) == 0) zPart[t >> 5][q] = v;
    }
    __syncthreads();
    if (t < NQ) {
        float v = 0.0f;
#pragma unroll
        for (int w = 0; w < NWARPS; w++) v += zPart[w][t];
        zFin[t] = v;
    }
    __syncthreads();

    // ======== linear head: out[b,o] = sum_q z[q] * W[o,q] + bias[o] ========
    if (t < NOUT) {
        float acc = bias[t];
#pragma unroll
        for (int q = 0; q < NQ; q++) acc = fmaf(zFin[q], W[t * NQ + q], acc);
        out[b * NOUT + t] = acc;
    }
}

extern "C" void kernel_launch(void* const* d_in, const int* in_sizes, int n_in,
                              void* d_out, int out_size) {
    const float* x     = (const float*)d_in[0];   // [4096, 12]
    const float* theta = (const float*)d_in[1];   // [144]
    const float* W     = (const float*)d_in[2];   // [10, 12]
    const float* bias  = (const float*)d_in[3];   // [10]
    float* out = (float*)d_out;                   // [4096, 10]
    (void)in_sizes; (void)n_in; (void)out_size;

    int batch = in_sizes[0] / NQ;                 // 4096
    qsim_kernel<<<batch, NTHREADS>>>(x, theta, W, bias, out);
}

// round 3
// speedup vs baseline: 1.0010x; 1.0010x over previous
#include <cuda_runtime.h>

// PennyLaneSimpleClassifier: 12-qubit state-vector sim, batch 4096.
// One CTA per batch element; state (4096 complex) lives in shared memory
// split into re/im float arrays with +1-word-per-32 padding.
//
// Circuit structure exploited:
//  - RY embedding == product state -> built from two 64-entry subproduct tables.
//  - RZ*RX*RZ fused into one 2x2 unitary per (layer, qubit)  (48 gates total).
//  - Adjacent-CNOT chain == Gray-code permutation: new[j] = old[j ^ (j>>1)].
//  - Each smem pass handles 4 qubits: thread owns 16 amplitudes, applies 4
//    register-resident butterfly stages. 3 gate passes + 1 perm per layer.
//  - Final permutation folded into the measurement read.

#define NQ 12
#define DIM 4096
#define NL 4
#define NOUT 10
#define NTHREADS 256
#define NWARPS (NTHREADS / 32)

__device__ __forceinline__ int pa(int i) { return i + (i >> 5); }  // bank-conflict padding

__device__ __forceinline__ float2 cmul(float2 a, float2 b) {
    return make_float2(fmaf(a.x, b.x, -a.y * b.y), fmaf(a.x, b.y, a.y * b.x));
}
__device__ __forceinline__ float2 cfma(float2 a, float2 b, float2 acc) {
    acc.x = fmaf(a.x, b.x, fmaf(-a.y, b.y, acc.x));
    acc.y = fmaf(a.x, b.y, fmaf(a.y, b.x, acc.y));
    return acc;
}

// Apply 4 butterfly stages (bits kb..kb+3) to a register-resident 16-amp group.
__device__ __forceinline__ void apply4(float2 amp[16], const float2 (*Ul)[4], int kb) {
#pragma unroll
    for (int s = 0; s < 4; s++) {
        int qub = 11 - (kb + s);              // amplitude bit (kb+s) == qubit 11-(kb+s)
        float2 m00 = Ul[qub][0];
        float2 m01 = Ul[qub][1];
        float2 m10 = Ul[qub][2];
        float2 m11 = Ul[qub][3];
#pragma unroll
        for (int v = 0; v < 16; v++) {
            if (v & (1 << s)) continue;
            float2 x0 = amp[v];
            float2 x1 = amp[v + (1 << s)];
            float2 y0 = cmul(m00, x0); y0 = cfma(m01, x1, y0);
            float2 y1 = cmul(m10, x0); y1 = cfma(m11, x1, y1);
            amp[v] = y0;
            amp[v + (1 << s)] = y1;
        }
    }
}

__global__ __launch_bounds__(NTHREADS)
void qsim_kernel(const float* __restrict__ x, const float* __restrict__ theta,
                 const float* __restrict__ W, const float* __restrict__ bias,
                 float* __restrict__ out)
{
    __shared__ float sRe[DIM + (DIM >> 5)];
    __shared__ float sIm[DIM + (DIM >> 5)];
    __shared__ float2 U[NL][NQ][4];
    __shared__ float prodLo[64], prodHi[64];
    __shared__ float cx[NQ], sx[NQ];
    __shared__ float zPart[NWARPS][NQ];
    __shared__ float zFin[NQ];

    const int b = blockIdx.x;
    const int t = threadIdx.x;

    // ---- fused RZ(c)*RX(bb)*RZ(a) gate matrices (48 of them) ----
    if (t < NL * NQ) {
        float a  = theta[3 * t + 0];
        float bb = theta[3 * t + 1];
        float c  = theta[3 * t + 2];
        float sh, ch;   sincosf(0.5f * bb, &sh, &ch);
        float sap, cap; sincosf(0.5f * (a + c), &sap, &cap);
        float sam, cam; sincosf(0.5f * (a - c), &sam, &cam);
        int l = t / NQ, q = t - l * NQ;
        U[l][q][0] = make_float2( ch * cap, -ch * sap);   // U00 =  cb e^{-i(a+c)/2}
        U[l][q][1] = make_float2( sh * sam, -sh * cam);   // U01 = -i sb e^{ i(a-c)/2}
        U[l][q][2] = make_float2(-sh * sam, -sh * cam);   // U10 = -i sb e^{-i(a-c)/2}
        U[l][q][3] = make_float2( ch * cap,  ch * sap);   // U11 =  cb e^{ i(a+c)/2}
    }
    // ---- RY embedding angles: cos/sin of x*pi/2 ----
    if (t < NQ) {
        float s, c;
        sincosf(x[b * NQ + t] * 1.57079632679489662f, &s, &c);
        sx[t] = s; cx[t] = c;
    }
    __syncthreads();

    // ---- subproduct tables for the product state ----
    if (t < 128) {
        int v = t & 63;
        float p = 1.0f;
        if (t < 64) {
            // amplitude bits 0..5 -> qubits 11..6
#pragma unroll
            for (int j = 0; j < 6; j++) p *= ((v >> j) & 1) ? sx[11 - j] : cx[11 - j];
            prodLo[v] = p;
        } else {
            // amplitude bits 6..11 -> qubits 5..0
#pragma unroll
            for (int j = 0; j < 6; j++) p *= ((v >> j) & 1) ? sx[5 - j] : cx[5 - j];
            prodHi[v] = p;
        }
    }

    float2 amp[16];
    const int g = t;  // group id: 256 groups of 16 amps

    for (int l = 0; l < NL; l++) {
        // ======== pass kb=8 : bits 8..11 (qubits 3..0) ========
        __syncthreads();
        if (l == 0) {
            // synthesize product state directly (init pass folded in)
#pragma unroll
            for (int v = 0; v < 16; v++) {
                int i = g + (v << 8);
                amp[v] = make_float2(prodHi[i >> 6] * prodLo[i & 63], 0.0f);
            }
        } else {
#pragma unroll
            for (int v = 0; v < 16; v++) {
                int idx = pa(g + (v << 8));
                amp[v] = make_float2(sRe[idx], sIm[idx]);
            }
        }
        apply4(amp, U[l], 8);
#pragma unroll
        for (int v = 0; v < 16; v++) {
            int idx = pa(g + (v << 8));
            sRe[idx] = amp[v].x; sIm[idx] = amp[v].y;
        }

        // ======== pass kb=4 : bits 4..7 (qubits 7..4) ========
        __syncthreads();
        {
            int ib = ((g >> 4) << 8) | (g & 15);
#pragma unroll
            for (int v = 0; v < 16; v++) {
                int idx = pa(ib + (v << 4));
                amp[v] = make_float2(sRe[idx], sIm[idx]);
            }
            apply4(amp, U[l], 4);
#pragma unroll
            for (int v = 0; v < 16; v++) {
                int idx = pa(ib + (v << 4));
                sRe[idx] = amp[v].x; sIm[idx] = amp[v].y;
            }
        }

        // ======== pass kb=0 : bits 0..3 (qubits 11..8) ========
        __syncthreads();
        {
            int ib = g << 4;
#pragma unroll
            for (int v = 0; v < 16; v++) {
                int idx = pa(ib + v);
                amp[v] = make_float2(sRe[idx], sIm[idx]);
            }
            apply4(amp, U[l], 0);
#pragma unroll
            for (int v = 0; v < 16; v++) {
                int idx = pa(ib + v);
                sRe[idx] = amp[v].x; sIm[idx] = amp[v].y;
            }
        }

        // ======== CNOT chain == Gray-code permutation ========
        if (l < NL - 1) {
            __syncthreads();
            float2 tmp[16];
#pragma unroll
            for (int m = 0; m < 16; m++) {
                int j = t + (m << 8);
                int idx = pa(j ^ (j >> 1));
                tmp[m] = make_float2(sRe[idx], sIm[idx]);
            }
            __syncthreads();
#pragma unroll
            for (int m = 0; m < 16; m++) {
                int idx = pa(t + (m << 8));
                sRe[idx] = tmp[m].x; sIm[idx] = tmp[m].y;
            }
        }
    }

    // ======== measurement (final permutation folded into the read) ========
    __syncthreads();
    // j = t + 256*m : bits 0..7 fixed per thread (qubits 4..11),
    //                 bits 8..11 = m (qubits 3..0, compile-time signs).
    float ptot = 0.0f, z0 = 0.0f, z1 = 0.0f, z2 = 0.0f, z3 = 0.0f;
#pragma unroll
    for (int m = 0; m < 16; m++) {
        int j = t + (m << 8);
        int idx = pa(j ^ (j >> 1));      // read the post-CNOT state
        float re = sRe[idx], im = sIm[idx];
        float pr = fmaf(re, re, im * im);
        ptot += pr;
        z0 += (m & 8) ? -pr : pr;        // qubit 0 = bit 11 = m bit 3
        z1 += (m & 4) ? -pr : pr;        // qubit 1
        z2 += (m & 2) ? -pr : pr;        // qubit 2
        z3 += (m & 1) ? -pr : pr;        // qubit 3
    }
    float zacc[NQ];
    zacc[0] = z0; zacc[1] = z1; zacc[2] = z2; zacc[3] = z3;
#pragma unroll
    for (int q = 4; q < NQ; q++)
        zacc[q] = ((t >> (11 - q)) & 1) ? -ptot : ptot;   // qubits 4..11 from thread bits

    // warp reduction, then cross-warp
#pragma unroll
    for (int q = 0; q < NQ; q++) {
        float v = zacc[q];
#pragma unroll
        for (int o = 16; o > 0; o >>= 1) v += __shfl_xor_sync(0xffffffffu, v, o);
        if ((t & 31) == 0) zPart[t >> 5][q] = v;
    }
    __syncthreads();
    if (t < NQ) {
        float v = 0.0f;
#pragma unroll
        for (int w = 0; w < NWARPS; w++) v += zPart[w][t];
        zFin[t] = v;
    }
    __syncthreads();

    // ======== linear head: out[b,o] = sum_q z[q] * W[o,q] + bias[o] ========
    if (t < NOUT) {
        float acc = bias[t];
#pragma unroll
        for (int q = 0; q < NQ; q++) acc = fmaf(zFin[q], W[t * NQ + q], acc);
        out[b * NOUT + t] = acc;
    }
}

extern "C" void kernel_launch(void* const* d_in, const int* in_sizes, int n_in,
                              void* d_out, int out_size) {
    const float* x     = (const float*)d_in[0];   // [4096, 12]
    const float* theta = (const float*)d_in[1];   // [144]
    const float* W     = (const float*)d_in[2];   // [10, 12]
    const float* bias  = (const float*)d_in[3];   // [10]
    float* out = (float*)d_out;                   // [4096, 10]
    (void)in_sizes; (void)n_in; (void)out_size;

    int batch = in_sizes[0] / NQ;                 // 4096
    qsim_kernel<<<batch, NTHREADS>>>(x, theta, W, bias, out);
}

// round 4
// speedup vs baseline: 1.1745x; 1.1733x over previous
#include <cuda_runtime.h>

// PennyLaneSimpleClassifier: 12-qubit state-vector sim, batch 4096.
// One CTA per batch element; state (4096 complex) lives in shared memory as
// float2 (packed re,im) with +1-slot-per-16 padding, accessed via LDS.64/STS.64.
//
// v3 changes vs v1:
//  - All butterfly arithmetic in packed fma.rn.f32x2 (FFMA2): 8 FFMA2 + 2
//    swaps per butterfly pair instead of 16 scalar FFMA.
//  - State stored as float2 -> half the LDS/STS instruction count.
//  - CNOT Gray-code permutation folded into the NEXT layer's first gather
//    (no dedicated permutation sweep at all).

#define NQ 12
#define DIM 4096
#define NL 4
#define NOUT 10
#define NTHREADS 256
#define NWARPS (NTHREADS / 32)

typedef unsigned long long ull;

__device__ __forceinline__ int pa2(int i) { return i + (i >> 4); }  // float2 padding

__device__ __forceinline__ ull packf2(float lo, float hi) {
    ull r; asm("mov.b64 %0, {%1,%2};" : "=l"(r) : "f"(lo), "f"(hi)); return r;
}
__device__ __forceinline__ ull f2swap(ull v) {
    ull r;
    asm("{\n\t.reg .b32 lo, hi;\n\tmov.b64 {lo,hi}, %1;\n\tmov.b64 %0, {hi,lo};\n\t}"
        : "=l"(r) : "l"(v));
    return r;
}
__device__ __forceinline__ ull f2mul(ull a, ull b) {
    ull r; asm("mul.rn.f32x2 %0, %1, %2;" : "=l"(r) : "l"(a), "l"(b)); return r;
}
__device__ __forceinline__ ull f2fma(ull a, ull b, ull c) {
    ull r; asm("fma.rn.f32x2 %0, %1, %2, %3;" : "=l"(r) : "l"(a), "l"(b), "l"(c)); return r;
}

// Apply 4 butterfly stages (amplitude bits kb..kb+3) to a 16-amp register group.
// Ul points at this layer's gate table: [NQ][8] ull, entry order
// {rr00, ii00, rr01, ii01, rr10, ii10, rr11, ii11} with rr={re,re}, ii={-im,im}.
__device__ __forceinline__ void apply4(ull amp[16], const ull* __restrict__ Ul, int kb) {
#pragma unroll
    for (int s = 0; s < 4; s++) {
        const ull* m = Ul + (11 - (kb + s)) * 8;   // amplitude bit kb+s == qubit 11-(kb+s)
        ull m0 = m[0], m1 = m[1], m2 = m[2], m3 = m[3];
        ull m4 = m[4], m5 = m[5], m6 = m[6], m7 = m[7];
        const int st = 1 << s;
#pragma unroll
        for (int v = 0; v < 16; v++) {
            if (v & st) continue;
            ull x0 = amp[v], x1 = amp[v + st];
            ull xs0 = f2swap(x0), xs1 = f2swap(x1);
            ull y0 = f2mul(m0, x0);
            y0 = f2fma(m1, xs0, y0);
            y0 = f2fma(m2, x1, y0);
            y0 = f2fma(m3, xs1, y0);
            ull y1 = f2mul(m4, x0);
            y1 = f2fma(m5, xs0, y1);
            y1 = f2fma(m6, x1, y1);
            y1 = f2fma(m7, xs1, y1);
            amp[v] = y0;
            amp[v + st] = y1;
        }
    }
}

__global__ __launch_bounds__(NTHREADS, 2)
void qsim_kernel(const float* __restrict__ x, const float* __restrict__ theta,
                 const float* __restrict__ W, const float* __restrict__ bias,
                 float* __restrict__ out)
{
    __shared__ ull sS[DIM + (DIM >> 4)];          // padded float2 state (34.8 KB)
    __shared__ ull Us[NL * NQ * 8];               // packed gate constants (3 KB)
    __shared__ float prodLo[64], prodHi[64];
    __shared__ float cx[NQ], sx[NQ];
    __shared__ float zPart[NWARPS][NQ];
    __shared__ float zFin[NQ];

    const int b = blockIdx.x;
    const int t = threadIdx.x;

    // ---- fused RZ(c)*RX(bb)*RZ(a) gate matrices, packed for f32x2 ----
    if (t < NL * NQ) {
        float a  = theta[3 * t + 0];
        float bb = theta[3 * t + 1];
        float c  = theta[3 * t + 2];
        float sh, ch;   sincosf(0.5f * bb, &sh, &ch);
        float sap, cap; sincosf(0.5f * (a + c), &sap, &cap);
        float sam, cam; sincosf(0.5f * (a - c), &sam, &cam);
        // U00 = ( ch*cap, -ch*sap)   U01 = ( sh*sam, -sh*cam)
        // U10 = (-sh*sam, -sh*cam)   U11 = ( ch*cap,  ch*sap)
        ull* u = &Us[t * 8];
        u[0] = packf2( ch * cap,  ch * cap);     // rr00
        u[1] = packf2( ch * sap, -ch * sap);     // ii00 = {-im, im}, im = -ch*sap
        u[2] = packf2( sh * sam,  sh * sam);     // rr01
        u[3] = packf2( sh * cam, -sh * cam);     // ii01, im = -sh*cam
        u[4] = packf2(-sh * sam, -sh * sam);     // rr10
        u[5] = packf2( sh * cam, -sh * cam);     // ii10, im = -sh*cam
        u[6] = packf2( ch * cap,  ch * cap);     // rr11
        u[7] = packf2(-ch * sap,  ch * sap);     // ii11, im = +ch*sap
    }
    // ---- RY embedding angles: cos/sin of x*pi/2 ----
    if (t < NQ) {
        float s, c;
        sincosf(x[b * NQ + t] * 1.57079632679489662f, &s, &c);
        sx[t] = s; cx[t] = c;
    }
    __syncthreads();

    // ---- subproduct tables for the product state ----
    if (t < 128) {
        int v = t & 63;
        float p = 1.0f;
        if (t < 64) {
            // amplitude bits 0..5 -> qubits 11..6
#pragma unroll
            for (int j = 0; j < 6; j++) p *= ((v >> j) & 1) ? sx[11 - j] : cx[11 - j];
            prodLo[v] = p;
        } else {
            // amplitude bits 6..11 -> qubits 5..0
#pragma unroll
            for (int j = 0; j < 6; j++) p *= ((v >> j) & 1) ? sx[5 - j] : cx[5 - j];
            prodHi[v] = p;
        }
    }
    __syncthreads();

    ull amp[16];
    const int g = t;  // 256 groups of 16 amplitudes

    for (int l = 0; l < NL; l++) {
        const ull* Ul = &Us[l * NQ * 8];

        // ======== pass kb=8 : bits 8..11 (qubits 3..0) ========
        // Gray-code permutation from the previous layer's CNOT chain is
        // folded into the gather for l >= 1.
        if (l == 0) {
#pragma unroll
            for (int v = 0; v < 16; v++) {
                int i = g + (v << 8);
                amp[v] = packf2(prodHi[i >> 6] * prodLo[i & 63], 0.0f);
            }
        } else {
#pragma unroll
            for (int v = 0; v < 16; v++) {
                int j = g + (v << 8);
                amp[v] = sS[pa2(j ^ (j >> 1))];
            }
        }
        apply4(amp, Ul, 8);
        if (l != 0) __syncthreads();   // all gathers done before scatter overwrites
#pragma unroll
        for (int v = 0; v < 16; v++)
            sS[pa2(g + (v << 8))] = amp[v];

        // ======== pass kb=4 : bits 4..7 (qubits 7..4) ========
        __syncthreads();
        {
            int ib = ((g >> 4) << 8) | (g & 15);
#pragma unroll
            for (int v = 0; v < 16; v++) amp[v] = sS[pa2(ib + (v << 4))];
            apply4(amp, Ul, 4);
#pragma unroll
            for (int v = 0; v < 16; v++) sS[pa2(ib + (v << 4))] = amp[v];
        }

        // ======== pass kb=0 : bits 0..3 (qubits 11..8) ========
        __syncthreads();
        {
            int ib = g << 4;
#pragma unroll
            for (int v = 0; v < 16; v++) amp[v] = sS[pa2(ib + v)];
            apply4(amp, Ul, 0);
#pragma unroll
            for (int v = 0; v < 16; v++) sS[pa2(ib + v)] = amp[v];
        }
        __syncthreads();
    }

    // ======== measurement (final CNOT permutation folded into the read) ====
    // j = t + 256*m : bits 0..7 per-thread (qubits 4..11),
    //                 bits 8..11 = m (qubits 3..0, compile-time signs).
    float ptot = 0.0f, z0 = 0.0f, z1 = 0.0f, z2 = 0.0f, z3 = 0.0f;
#pragma unroll
    for (int m = 0; m < 16; m++) {
        int j = t + (m << 8);
        ull a = sS[pa2(j ^ (j >> 1))];
        float2 f = *reinterpret_cast<float2*>(&a);
        float pr = fmaf(f.x, f.x, f.y * f.y);
        ptot += pr;
        z0 += (m & 8) ? -pr : pr;   // qubit 0 = amplitude bit 11 = m bit 3
        z1 += (m & 4) ? -pr : pr;
        z2 += (m & 2) ? -pr : pr;
        z3 += (m & 1) ? -pr : pr;
    }
    float zacc[NQ];
    zacc[0] = z0; zacc[1] = z1; zacc[2] = z2; zacc[3] = z3;
#pragma unroll
    for (int q = 4; q < NQ; q++)
        zacc[q] = ((t >> (11 - q)) & 1) ? -ptot : ptot;  // qubits 4..11 from thread bits

#pragma unroll
    for (int q = 0; q < NQ; q++) {
        float v = zacc[q];
#pragma unroll
        for (int o = 16; o > 0; o >>= 1) v += __shfl_xor_sync(0xffffffffu, v, o);
        if ((t & 31) == 0) zPart[t >> 5][q] = v;
    }
    __syncthreads();
    if (t < NQ) {
        float v = 0.0f;
#pragma unroll
        for (int w = 0; w < NWARPS; w++) v += zPart[w][t];
        zFin[t] = v;
    }
    __syncthreads();

    // ======== linear head: out[b,o] = sum_q z[q] * W[o,q] + bias[o] ========
    if (t < NOUT) {
        float acc = bias[t];
#pragma unroll
        for (int q = 0; q < NQ; q++) acc = fmaf(zFin[q], W[t * NQ + q], acc);
        out[b * NOUT + t] = acc;
    }
}

extern "C" void kernel_launch(void* const* d_in, const int* in_sizes, int n_in,
                              void* d_out, int out_size) {
    const float* x     = (const float*)d_in[0];   // [4096, 12]
    const float* theta = (const float*)d_in[1];   // [144]
    const float* W     = (const float*)d_in[2];   // [10, 12]
    const float* bias  = (const float*)d_in[3];   // [10]
    float* out = (float*)d_out;                   // [4096, 10]
    (void)n_in; (void)out_size;

    int batch = in_sizes[0] / NQ;                 // 4096
    qsim_kernel<<<batch, NTHREADS>>>(x, theta, W, bias, out);
}

// round 5
// speedup vs baseline: 1.1754x; 1.0008x over previous
#include <cuda_runtime.h>

// PennyLaneSimpleClassifier: 12-qubit state-vector sim, batch 4096.
// One CTA per batch element; state (4096 complex) lives in shared memory as
// float2 (packed re,im) with +1-slot-per-16 padding, accessed via LDS.64/STS.64.
//
// v3 changes vs v1:
//  - All butterfly arithmetic in packed fma.rn.f32x2 (FFMA2): 8 FFMA2 + 2
//    swaps per butterfly pair instead of 16 scalar FFMA.
//  - State stored as float2 -> half the LDS/STS instruction count.
//  - CNOT Gray-code permutation folded into the NEXT layer's first gather
//    (no dedicated permutation sweep at all).

#define NQ 12
#define DIM 4096
#define NL 4
#define NOUT 10
#define NTHREADS 256
#define NWARPS (NTHREADS / 32)

typedef unsigned long long ull;

__device__ __forceinline__ int pa2(int i) { return i + (i >> 4); }  // float2 padding

__device__ __forceinline__ ull packf2(float lo, float hi) {
    ull r; asm("mov.b64 %0, {%1,%2};" : "=l"(r) : "f"(lo), "f"(hi)); return r;
}
__device__ __forceinline__ ull f2swap(ull v) {
    ull r;
    asm("{\n\t.reg .b32 lo, hi;\n\tmov.b64 {lo,hi}, %1;\n\tmov.b64 %0, {hi,lo};\n\t}"
        : "=l"(r) : "l"(v));
    return r;
}
__device__ __forceinline__ ull f2mul(ull a, ull b) {
    ull r; asm("mul.rn.f32x2 %0, %1, %2;" : "=l"(r) : "l"(a), "l"(b)); return r;
}
__device__ __forceinline__ ull f2fma(ull a, ull b, ull c) {
    ull r; asm("fma.rn.f32x2 %0, %1, %2, %3;" : "=l"(r) : "l"(a), "l"(b), "l"(c)); return r;
}

// Apply 4 butterfly stages (amplitude bits kb..kb+3) to a 16-amp register group.
// Ul points at this layer's gate table: [NQ][8] ull, entry order
// {rr00, ii00, rr01, ii01, rr10, ii10, rr11, ii11} with rr={re,re}, ii={-im,im}.
__device__ __forceinline__ void apply4(ull amp[16], const ull* __restrict__ Ul, int kb) {
#pragma unroll
    for (int s = 0; s < 4; s++) {
        const ull* m = Ul + (11 - (kb + s)) * 8;   // amplitude bit kb+s == qubit 11-(kb+s)
        ull m0 = m[0], m1 = m[1], m2 = m[2], m3 = m[3];
        ull m4 = m[4], m5 = m[5], m6 = m[6], m7 = m[7];
        const int st = 1 << s;
#pragma unroll
        for (int v = 0; v < 16; v++) {
            if (v & st) continue;
            ull x0 = amp[v], x1 = amp[v + st];
            ull xs0 = f2swap(x0), xs1 = f2swap(x1);
            ull y0 = f2mul(m0, x0);
            y0 = f2fma(m1, xs0, y0);
            y0 = f2fma(m2, x1, y0);
            y0 = f2fma(m3, xs1, y0);
            ull y1 = f2mul(m4, x0);
            y1 = f2fma(m5, xs0, y1);
            y1 = f2fma(m6, x1, y1);
            y1 = f2fma(m7, xs1, y1);
            amp[v] = y0;
            amp[v + st] = y1;
        }
    }
}

__global__ __launch_bounds__(NTHREADS, 2)
void qsim_kernel(const float* __restrict__ x, const float* __restrict__ theta,
                 const float* __restrict__ W, const float* __restrict__ bias,
                 float* __restrict__ out)
{
    __shared__ ull sS[DIM + (DIM >> 4)];          // padded float2 state (34.8 KB)
    __shared__ ull Us[NL * NQ * 8];               // packed gate constants (3 KB)
    __shared__ float prodLo[64], prodHi[64];
    __shared__ float cx[NQ], sx[NQ];
    __shared__ float zPart[NWARPS][NQ];
    __shared__ float zFin[NQ];

    const int b = blockIdx.x;
    const int t = threadIdx.x;

    // ---- fused RZ(c)*RX(bb)*RZ(a) gate matrices, packed for f32x2 ----
    if (t < NL * NQ) {
        float a  = theta[3 * t + 0];
        float bb = theta[3 * t + 1];
        float c  = theta[3 * t + 2];
        float sh, ch;   sincosf(0.5f * bb, &sh, &ch);
        float sap, cap; sincosf(0.5f * (a + c), &sap, &cap);
        float sam, cam; sincosf(0.5f * (a - c), &sam, &cam);
        // U00 = ( ch*cap, -ch*sap)   U01 = ( sh*sam, -sh*cam)
        // U10 = (-sh*sam, -sh*cam)   U11 = ( ch*cap,  ch*sap)
        ull* u = &Us[t * 8];
        u[0] = packf2( ch * cap,  ch * cap);     // rr00
        u[1] = packf2( ch * sap, -ch * sap);     // ii00 = {-im, im}, im = -ch*sap
        u[2] = packf2( sh * sam,  sh * sam);     // rr01
        u[3] = packf2( sh * cam, -sh * cam);     // ii01, im = -sh*cam
        u[4] = packf2(-sh * sam, -sh * sam);     // rr10
        u[5] = packf2( sh * cam, -sh * cam);     // ii10, im = -sh*cam
        u[6] = packf2( ch * cap,  ch * cap);     // rr11
        u[7] = packf2(-ch * sap,  ch * sap);     // ii11, im = +ch*sap
    }
    // ---- RY embedding angles: cos/sin of x*pi/2 ----
    if (t < NQ) {
        float s, c;
        sincosf(x[b * NQ + t] * 1.57079632679489662f, &s, &c);
        sx[t] = s; cx[t] = c;
    }
    __syncthreads();

    // ---- subproduct tables for the product state ----
    if (t < 128) {
        int v = t & 63;
        float p = 1.0f;
        if (t < 64) {
            // amplitude bits 0..5 -> qubits 11..6
#pragma unroll
            for (int j = 0; j < 6; j++) p *= ((v >> j) & 1) ? sx[11 - j] : cx[11 - j];
            prodLo[v] = p;
        } else {
            // amplitude bits 6..11 -> qubits 5..0
#pragma unroll
            for (int j = 0; j < 6; j++) p *= ((v >> j) & 1) ? sx[5 - j] : cx[5 - j];
            prodHi[v] = p;
        }
    }
    __syncthreads();

    ull amp[16];
    const int g = t;  // 256 groups of 16 amplitudes

    for (int l = 0; l < NL; l++) {
        const ull* Ul = &Us[l * NQ * 8];

        // ======== pass kb=8 : bits 8..11 (qubits 3..0) ========
        // Gray-code permutation from the previous layer's CNOT chain is
        // folded into the gather for l >= 1.
        if (l == 0) {
#pragma unroll
            for (int v = 0; v < 16; v++) {
                int i = g + (v << 8);
                amp[v] = packf2(prodHi[i >> 6] * prodLo[i & 63], 0.0f);
            }
        } else {
#pragma unroll
            for (int v = 0; v < 16; v++) {
                int j = g + (v << 8);
                amp[v] = sS[pa2(j ^ (j >> 1))];
            }
        }
        apply4(amp, Ul, 8);
        if (l != 0) __syncthreads();   // all gathers done before scatter overwrites
#pragma unroll
        for (int v = 0; v < 16; v++)
            sS[pa2(g + (v << 8))] = amp[v];

        // ======== pass kb=4 : bits 4..7 (qubits 7..4) ========
        __syncthreads();
        {
            int ib = ((g >> 4) << 8) | (g & 15);
#pragma unroll
            for (int v = 0; v < 16; v++) amp[v] = sS[pa2(ib + (v << 4))];
            apply4(amp, Ul, 4);
#pragma unroll
            for (int v = 0; v < 16; v++) sS[pa2(ib + (v << 4))] = amp[v];
        }

        // ======== pass kb=0 : bits 0..3 (qubits 11..8) ========
        __syncthreads();
        {
            int ib = g << 4;
#pragma unroll
            for (int v = 0; v < 16; v++) amp[v] = sS[pa2(ib + v)];
            apply4(amp, Ul, 0);
#pragma unroll
            for (int v = 0; v < 16; v++) sS[pa2(ib + v)] = amp[v];
        }
        __syncthreads();
    }

    // ======== measurement (final CNOT permutation folded into the read) ====
    // j = t + 256*m : bits 0..7 per-thread (qubits 4..11),
    //                 bits 8..11 = m (qubits 3..0, compile-time signs).
    float ptot = 0.0f, z0 = 0.0f, z1 = 0.0f, z2 = 0.0f, z3 = 0.0f;
#pragma unroll
    for (int m = 0; m < 16; m++) {
        int j = t + (m << 8);
        ull a = sS[pa2(j ^ (j >> 1))];
        float2 f = *reinterpret_cast<float2*>(&a);
        float pr = fmaf(f.x, f.x, f.y * f.y);
        ptot += pr;
        z0 += (m & 8) ? -pr : pr;   // qubit 0 = amplitude bit 11 = m bit 3
        z1 += (m & 4) ? -pr : pr;
        z2 += (m & 2) ? -pr : pr;
        z3 += (m & 1) ? -pr : pr;
    }
    float zacc[NQ];
    zacc[0] = z0; zacc[1] = z1; zacc[2] = z2; zacc[3] = z3;
#pragma unroll
    for (int q = 4; q < NQ; q++)
        zacc[q] = ((t >> (11 - q)) & 1) ? -ptot : ptot;  // qubits 4..11 from thread bits

#pragma unroll
    for (int q = 0; q < NQ; q++) {
        float v = zacc[q];
#pragma unroll
        for (int o = 16; o > 0; o >>= 1) v += __shfl_xor_sync(0xffffffffu, v, o);
        if ((t & 31) == 0) zPart[t >> 5][q] = v;
    }
    __syncthreads();
    if (t < NQ) {
        float v = 0.0f;
#pragma unroll
        for (int w = 0; w < NWARPS; w++) v += zPart[w][t];
        zFin[t] = v;
    }
    __syncthreads();

    // ======== linear head: out[b,o] = sum_q z[q] * W[o,q] + bias[o] ========
    if (t < NOUT) {
        float acc = bias[t];
#pragma unroll
        for (int q = 0; q < NQ; q++) acc = fmaf(zFin[q], W[t * NQ + q], acc);
        out[b * NOUT + t] = acc;
    }
}

extern "C" void kernel_launch(void* const* d_in, const int* in_sizes, int n_in,
                              void* d_out, int out_size) {
    const float* x     = (const float*)d_in[0];   // [4096, 12]
    const float* theta = (const float*)d_in[1];   // [144]
    const float* W     = (const float*)d_in[2];   // [10, 12]
    const float* bias  = (const float*)d_in[3];   // [10]
    float* out = (float*)d_out;                   // [4096, 10]
    (void)n_in; (void)out_size;

    int batch = in_sizes[0] / NQ;                 // 4096
    qsim_kernel<<<batch, NTHREADS>>>(x, theta, W, bias, out);
}